// round 3
// baseline (speedup 1.0000x reference)
#include <cuda_runtime.h>
#include <cuda_bf16.h>
#include <cstdint>

using bf16 = __nv_bfloat16;

#define DEVINLINE __device__ __forceinline__

static constexpr int CH    = 512;
static constexpr int HWDIM = 1024;
static constexpr int BATCH = 32;
static constexpr int NALL  = BATCH * HWDIM;   // 32768

// ---------------- scratch (device globals; no allocation allowed) -----------
__device__ bf16  g_W   [4 * CH * CH];                    // Wq,Wk,Wv,Wo bf16
__device__ bf16  g_XT  [(size_t)NALL * CH];              // [b*HW+s][c]
__device__ bf16  g_QK  [(size_t)NALL * 2 * CH];          // [s][0:512)=q, [512:1024)=k
__device__ bf16  g_V   [(size_t)CH * NALL];              // [c][b*HW+s]
__device__ bf16  g_P   [(size_t)BATCH * HWDIM * HWDIM];  // exp(scores) bf16
__device__ float g_RS  [NALL];                           // 1/rowsum
__device__ bf16  g_HT  [(size_t)NALL * CH];              // [b*HW+s][c]

// ---------------- helpers ----------------------------------------------------
DEVINLINE void ldsm4(uint32_t& r0, uint32_t& r1, uint32_t& r2, uint32_t& r3,
                     const bf16* p) {
    uint32_t addr = (uint32_t)__cvta_generic_to_shared(p);
    asm volatile("ldmatrix.sync.aligned.m8n8.x4.shared.b16 {%0,%1,%2,%3}, [%4];"
                 : "=r"(r0), "=r"(r1), "=r"(r2), "=r"(r3) : "r"(addr));
}

DEVINLINE void mma_bf16(float c[4], const uint32_t a[4], const uint32_t b[2]) {
    asm volatile("mma.sync.aligned.m16n8k16.row.col.f32.bf16.bf16.f32 "
                 "{%0,%1,%2,%3},{%4,%5,%6,%7},{%8,%9},{%0,%1,%2,%3};"
                 : "+f"(c[0]), "+f"(c[1]), "+f"(c[2]), "+f"(c[3])
                 : "r"(a[0]), "r"(a[1]), "r"(a[2]), "r"(a[3]),
                   "r"(b[0]), "r"(b[1]));
}

DEVINLINE void cp16(bf16* dst, const bf16* src) {
    uint32_t d = (uint32_t)__cvta_generic_to_shared(dst);
    asm volatile("cp.async.cg.shared.global [%0], [%1], 16;" :: "r"(d), "l"(src));
}
DEVINLINE void cp_commit() { asm volatile("cp.async.commit_group;"); }
DEVINLINE void cp_wait0()  { asm volatile("cp.async.wait_group 0;"); }

// ---------------- prep kernels -----------------------------------------------
__global__ void convert_w_kernel(const float* __restrict__ wq,
                                 const float* __restrict__ wk,
                                 const float* __restrict__ wv,
                                 const float* __restrict__ wo,
                                 bf16* __restrict__ W) {
    int i = blockIdx.x * blockDim.x + threadIdx.x;
    W[i]               = __float2bfloat16(wq[i]);
    W[i + CH * CH]     = __float2bfloat16(wk[i]);
    W[i + 2 * CH * CH] = __float2bfloat16(wv[i]);
    W[i + 3 * CH * CH] = __float2bfloat16(wo[i]);
}

// x [B][C][HW] fp32 -> XT [B*HW][C] bf16
__global__ void xt_kernel(const float* __restrict__ x, bf16* __restrict__ XT) {
    __shared__ float tile[32][33];
    const int b  = blockIdx.z;
    const int s0 = blockIdx.x * 32;
    const int c0 = blockIdx.y * 32;
    const int tx = threadIdx.x, ty = threadIdx.y;
    tile[ty][tx] = x[((size_t)b * CH + c0 + ty) * HWDIM + s0 + tx];
    __syncthreads();
    XT[((size_t)b * HWDIM + s0 + ty) * CH + c0 + tx] = __float2bfloat16(tile[tx][ty]);
}

// 1/rowsum of P (exp-scores); warp per row
__global__ void rowsum_kernel(const bf16* __restrict__ P, float* __restrict__ RS) {
    const int row  = blockIdx.x * 8 + (threadIdx.x >> 5);
    const int lane = threadIdx.x & 31;
    const uint4* p = (const uint4*)(P + (size_t)row * HWDIM);
    float s = 0.f;
    #pragma unroll
    for (int j = 0; j < 4; ++j) {
        uint4 v = p[lane + j * 32];
        const __nv_bfloat162* h = (const __nv_bfloat162*)&v;
        #pragma unroll
        for (int t = 0; t < 4; ++t) {
            float2 f = __bfloat1622float2(h[t]);
            s += f.x + f.y;
        }
    }
    #pragma unroll
    for (int o = 16; o > 0; o >>= 1) s += __shfl_xor_sync(0xffffffffu, s, o);
    if (lane == 0) RS[row] = 1.f / s;
}

// ---------------- GEMM: C[m,n] = sum_k A[m,k]*B[n,k] -------------------------
// Block tile 256x128, BK=32, 8 warps of 64x64. cp.async double buffered.
// EPI 0: bf16 out, dual col-bias (cols [0,512)->bias1, [512,1024)->bias2)
// EPI 1: bf16 out, per-row bias
// EPI 2: bf16 out = exp(acc*scale)   (fused exp-scores)
// EPI 3: fp32 out at [b][m][s] (n=b*1024+s), row bias + residual
// EPI 4: bf16 out, row-scaled by aux[z*1024 + r]   (PV / softmax denom)
template<int EPI>
__global__ void __launch_bounds__(256)
gemm_kernel(const bf16* __restrict__ A, const bf16* __restrict__ B,
            void* __restrict__ Cout,
            int K, int lda, int ldb, int ldc,
            size_t sA_batch, size_t sB_batch, size_t sC_batch,
            const float* __restrict__ bias1,
            const float* __restrict__ bias2,
            const float* __restrict__ aux,
            float scale)
{
    constexpr int BM = 256, BN = 128, BK = 32;
    constexpr int LDS = BK + 8;
    constexpr int ASZ = BM * LDS;    // elems per A buffer
    constexpr int BSZ = BN * LDS;
    extern __shared__ bf16 smem[];
    bf16* sA = smem;                 // 2 buffers
    bf16* sB = smem + 2 * ASZ;

    const int tid  = threadIdx.x;
    const int lane = tid & 31;
    const int warp = tid >> 5;
    const int wm   = warp >> 1;      // 0..3 -> 64 rows
    const int wn   = warp & 1;       // 0..1 -> 64 cols
    const int bm0  = blockIdx.y * BM;
    const int bn0  = blockIdx.x * BN;
    const int z    = blockIdx.z;

    const bf16* Ab = A + (size_t)z * sA_batch;
    const bf16* Bb = B + (size_t)z * sB_batch;

    const int grow = tid >> 2;          // 0..63
    const int gcol = (tid & 3) * 8;     // 0,8,16,24

    const bf16* gA = Ab + (size_t)(bm0 + grow) * lda + gcol;
    const bf16* gB = Bb + (size_t)(bn0 + grow) * ldb + gcol;
    bf16* swA = sA + grow * LDS + gcol;
    bf16* swB = sB + grow * LDS + gcol;

    const int nk = K / BK;

    // tile 0
    #pragma unroll
    for (int i = 0; i < 4; ++i) cp16(swA + i * 64 * LDS, gA + (size_t)i * 64 * lda);
    #pragma unroll
    for (int i = 0; i < 2; ++i) cp16(swB + i * 64 * LDS, gB + (size_t)i * 64 * ldb);
    cp_commit();

    float acc[4][8][4];
    #pragma unroll
    for (int i = 0; i < 4; ++i)
        #pragma unroll
        for (int j = 0; j < 8; ++j)
            #pragma unroll
            for (int l = 0; l < 4; ++l) acc[i][j][l] = 0.f;

    const int a_base = (wm * 64 + (lane & 15)) * LDS + (lane >> 4) * 8;
    const int b_base = (wn * 64 + (lane & 7) + ((lane >> 4) & 1) * 8) * LDS
                     + ((lane >> 3) & 1) * 8;

    cp_wait0();
    __syncthreads();

    for (int kt = 0; kt < nk; ++kt) {
        const int cur = kt & 1;
        const bool pf = (kt + 1 < nk);
        if (pf) {
            const int nxt = cur ^ 1;
            const size_t ko = (size_t)(kt + 1) * BK;
            bf16* dA = swA + nxt * ASZ;
            bf16* dB = swB + nxt * BSZ;
            #pragma unroll
            for (int i = 0; i < 4; ++i) cp16(dA + i * 64 * LDS, gA + (size_t)i * 64 * lda + ko);
            #pragma unroll
            for (int i = 0; i < 2; ++i) cp16(dB + i * 64 * LDS, gB + (size_t)i * 64 * ldb + ko);
            cp_commit();
        }

        const bf16* ca = sA + cur * ASZ;
        const bf16* cb = sB + cur * BSZ;
        #pragma unroll
        for (int ks = 0; ks < 2; ++ks) {
            uint32_t af[4][4];
            #pragma unroll
            for (int mf = 0; mf < 4; ++mf)
                ldsm4(af[mf][0], af[mf][1], af[mf][2], af[mf][3],
                      &ca[a_base + mf * 16 * LDS + ks * 16]);
            uint32_t bg[8][2];
            #pragma unroll
            for (int pr = 0; pr < 4; ++pr)
                ldsm4(bg[2 * pr][0], bg[2 * pr][1], bg[2 * pr + 1][0], bg[2 * pr + 1][1],
                      &cb[b_base + pr * 16 * LDS + ks * 16]);
            #pragma unroll
            for (int mf = 0; mf < 4; ++mf)
                #pragma unroll
                for (int nf = 0; nf < 8; ++nf)
                    mma_bf16(acc[mf][nf], af[mf], bg[nf]);
        }

        if (pf) cp_wait0();
        __syncthreads();
    }

    const int r_base = bm0 + wm * 64 + (lane >> 2);
    const int c_base = bn0 + wn * 64 + ((lane & 3) << 1);

    #pragma unroll
    for (int mf = 0; mf < 4; ++mf) {
        #pragma unroll
        for (int nf = 0; nf < 8; ++nf) {
            const int r = r_base + mf * 16;
            const int c = c_base + nf * 8;
            const float* a4 = acc[mf][nf];

            if (EPI == 0) {
                bf16* outp = (bf16*)Cout + (size_t)z * sC_batch;
                float b0 = 0.f, b1 = 0.f;
                if (c < 512) { if (bias1) { b0 = bias1[c]; b1 = bias1[c + 1]; } }
                else         { if (bias2) { b0 = bias2[c - 512]; b1 = bias2[c - 511]; } }
                *(__nv_bfloat162*)(outp + (size_t)r * ldc + c) =
                    __floats2bfloat162_rn(a4[0] + b0, a4[1] + b1);
                *(__nv_bfloat162*)(outp + (size_t)(r + 8) * ldc + c) =
                    __floats2bfloat162_rn(a4[2] + b0, a4[3] + b1);
            } else if (EPI == 1) {
                bf16* outp = (bf16*)Cout + (size_t)z * sC_batch;
                const float rb0 = bias1 ? bias1[r] : 0.f;
                const float rb1 = bias1 ? bias1[r + 8] : 0.f;
                *(__nv_bfloat162*)(outp + (size_t)r * ldc + c) =
                    __floats2bfloat162_rn(a4[0] + rb0, a4[1] + rb0);
                *(__nv_bfloat162*)(outp + (size_t)(r + 8) * ldc + c) =
                    __floats2bfloat162_rn(a4[2] + rb1, a4[3] + rb1);
            } else if (EPI == 2) {
                bf16* outp = (bf16*)Cout + (size_t)z * sC_batch;
                *(__nv_bfloat162*)(outp + (size_t)r * ldc + c) =
                    __floats2bfloat162_rn(__expf(a4[0] * scale), __expf(a4[1] * scale));
                *(__nv_bfloat162*)(outp + (size_t)(r + 8) * ldc + c) =
                    __floats2bfloat162_rn(__expf(a4[2] * scale), __expf(a4[3] * scale));
            } else if (EPI == 4) {
                bf16* outp = (bf16*)Cout + (size_t)z * sC_batch;
                const float rs0 = aux[z * HWDIM + r];
                const float rs1 = aux[z * HWDIM + r + 8];
                *(__nv_bfloat162*)(outp + (size_t)r * ldc + c) =
                    __floats2bfloat162_rn(a4[0] * rs0, a4[1] * rs0);
                *(__nv_bfloat162*)(outp + (size_t)(r + 8) * ldc + c) =
                    __floats2bfloat162_rn(a4[2] * rs1, a4[3] * rs1);
            } else {   // EPI == 3 final out + residual
                float* outp = (float*)Cout;
                const int bb = c >> 10;
                const int s  = c & 1023;
                const size_t i0 = (size_t)bb * (CH * HWDIM) + (size_t)r * HWDIM + s;
                const size_t i1 = i0 + 8 * HWDIM;
                const float br0 = bias1 ? bias1[r] : 0.f;
                const float br1 = bias1 ? bias1[r + 8] : 0.f;
                const float2 x0 = *(const float2*)(aux + i0);
                const float2 x1 = *(const float2*)(aux + i1);
                *(float2*)(outp + i0) = make_float2(a4[0] + br0 + x0.x, a4[1] + br0 + x0.y);
                *(float2*)(outp + i1) = make_float2(a4[2] + br1 + x1.x, a4[3] + br1 + x1.y);
            }
        }
    }
}

// ---------------- launch ------------------------------------------------------
static constexpr int GEMM_SMEM =
    (2 * 256 * 40 + 2 * 128 * 40) * (int)sizeof(bf16);   // 61440 B

extern "C" void kernel_launch(void* const* d_in, const int* in_sizes, int n_in,
                              void* d_out, int out_size)
{
    (void)in_sizes; (void)n_in; (void)out_size;
    const float* x  = (const float*)d_in[0];
    const float* Wq = (const float*)d_in[1];
    const float* bq = (const float*)d_in[2];
    const float* Wk = (const float*)d_in[3];
    const float* bk = (const float*)d_in[4];
    const float* Wv = (const float*)d_in[5];
    const float* bv = (const float*)d_in[6];
    const float* Wo = (const float*)d_in[7];
    const float* bo = (const float*)d_in[8];
    float* out = (float*)d_out;

    bf16 *pW, *pXT, *pQK, *pV, *pP, *pHT;
    float *pRS;
    cudaGetSymbolAddress((void**)&pW,  g_W);
    cudaGetSymbolAddress((void**)&pXT, g_XT);
    cudaGetSymbolAddress((void**)&pQK, g_QK);
    cudaGetSymbolAddress((void**)&pV,  g_V);
    cudaGetSymbolAddress((void**)&pP,  g_P);
    cudaGetSymbolAddress((void**)&pRS, g_RS);
    cudaGetSymbolAddress((void**)&pHT, g_HT);

    cudaFuncSetAttribute(gemm_kernel<0>, cudaFuncAttributeMaxDynamicSharedMemorySize, GEMM_SMEM);
    cudaFuncSetAttribute(gemm_kernel<1>, cudaFuncAttributeMaxDynamicSharedMemorySize, GEMM_SMEM);
    cudaFuncSetAttribute(gemm_kernel<2>, cudaFuncAttributeMaxDynamicSharedMemorySize, GEMM_SMEM);
    cudaFuncSetAttribute(gemm_kernel<3>, cudaFuncAttributeMaxDynamicSharedMemorySize, GEMM_SMEM);
    cudaFuncSetAttribute(gemm_kernel<4>, cudaFuncAttributeMaxDynamicSharedMemorySize, GEMM_SMEM);

    // prep
    convert_w_kernel<<<(CH * CH) / 256, 256>>>(Wq, Wk, Wv, Wo, pW);
    xt_kernel<<<dim3(HWDIM / 32, CH / 32, BATCH), dim3(32, 32)>>>(x, pXT);

    // QK = XT * [Wq|Wk]^T : M=32768, N=1024, K=512
    gemm_kernel<0><<<dim3(1024 / 128, NALL / 256, 1), 256, GEMM_SMEM>>>(
        pXT, pW, pQK, CH, CH, CH, 1024, 0, 0, 0, bq, bk, nullptr, 1.f);

    // V = Wv * X^T (+bv rows) : M=512, N=32768, K=512, out [c][s]
    gemm_kernel<1><<<dim3(NALL / 128, CH / 256, 1), 256, GEMM_SMEM>>>(
        pW + 2 * CH * CH, pXT, pV, CH, CH, CH, NALL, 0, 0, 0, bv, nullptr, nullptr, 1.f);

    // P_b = exp(scale * Q_b K_b^T) : per-batch, M=N=1024, K=512
    gemm_kernel<2><<<dim3(HWDIM / 128, HWDIM / 256, BATCH), 256, GEMM_SMEM>>>(
        pQK, pQK + 512, pP, CH, 1024, 1024, HWDIM,
        (size_t)HWDIM * 1024, (size_t)HWDIM * 1024, (size_t)HWDIM * HWDIM,
        nullptr, nullptr, nullptr, 0.04419417382415922f);

    // 1 / rowsums of P
    rowsum_kernel<<<NALL / 8, 256>>>(pP, pRS);

    // HT_b = (P_b * V_b^T) * rsinv : M=1024, N=512, K=1024
    gemm_kernel<4><<<dim3(CH / 128, HWDIM / 256, BATCH), 256, GEMM_SMEM>>>(
        pP, pV, pHT, HWDIM, HWDIM, NALL, CH,
        (size_t)HWDIM * HWDIM, (size_t)HWDIM, (size_t)HWDIM * CH,
        nullptr, nullptr, pRS, 1.f);

    // O = Wo * HT^T + bo + x : M=512, N=32768, K=512
    gemm_kernel<3><<<dim3(NALL / 128, CH / 256, 1), 256, GEMM_SMEM>>>(
        pW + 3 * CH * CH, pHT, out, CH, CH, CH, 0,
        0, 0, 0, bo, nullptr, x, 1.f);
}

// round 5
// speedup vs baseline: 1.2630x; 1.2630x over previous
#include <cuda_runtime.h>
#include <cuda_fp16.h>
#include <cstdint>

using f16 = __half;
#define DEVINLINE __device__ __forceinline__

static constexpr int CH    = 512;
static constexpr int HWDIM = 1024;
static constexpr int BATCH = 32;
static constexpr int NALL  = BATCH * HWDIM;   // 32768

static constexpr float WO_SCALE   = 4096.f;
static constexpr float WO_UNSCALE = 1.f / 4096.f;

// ---------------- scratch ----------------------------------------------------
__device__ f16   g_W [4 * CH * CH];
__device__ f16   g_XT[(size_t)NALL * CH];
__device__ f16   g_QK[(size_t)NALL * 2 * CH];
__device__ f16   g_V [(size_t)CH * NALL];
__device__ f16   g_P [(size_t)BATCH * HWDIM * HWDIM];
__device__ float g_RS[NALL];
__device__ f16   g_HT[(size_t)NALL * CH];

// ---------------- helpers ------------------------------------------------------
DEVINLINE void ldsm4(uint32_t& r0, uint32_t& r1, uint32_t& r2, uint32_t& r3,
                     const f16* p) {
    uint32_t addr = (uint32_t)__cvta_generic_to_shared(p);
    asm volatile("ldmatrix.sync.aligned.m8n8.x4.shared.b16 {%0,%1,%2,%3}, [%4];"
                 : "=r"(r0), "=r"(r1), "=r"(r2), "=r"(r3) : "r"(addr));
}

DEVINLINE void mma_f16(uint32_t c[2], const uint32_t a[4], const uint32_t b[2]) {
    asm volatile("mma.sync.aligned.m16n8k16.row.col.f16.f16.f16.f16 "
                 "{%0,%1},{%2,%3,%4,%5},{%6,%7},{%0,%1};"
                 : "+r"(c[0]), "+r"(c[1])
                 : "r"(a[0]), "r"(a[1]), "r"(a[2]), "r"(a[3]),
                   "r"(b[0]), "r"(b[1]));
}

DEVINLINE void cp16(f16* dst, const f16* src) {
    uint32_t d = (uint32_t)__cvta_generic_to_shared(dst);
    asm volatile("cp.async.cg.shared.global [%0], [%1], 16;" :: "r"(d), "l"(src));
}
DEVINLINE void cp_commit() { asm volatile("cp.async.commit_group;"); }
template<int N> DEVINLINE void cp_wait() {
    asm volatile("cp.async.wait_group %0;" :: "n"(N));
}

// ---------------- prep kernels ---------------------------------------------------
__global__ void convert_w_kernel(const float* __restrict__ wq, const float* __restrict__ wk,
                                 const float* __restrict__ wv, const float* __restrict__ wo,
                                 f16* __restrict__ W) {
    int i = blockIdx.x * blockDim.x + threadIdx.x;
    W[i]               = __float2half(wq[i]);
    W[i + CH * CH]     = __float2half(wk[i]);
    W[i + 2 * CH * CH] = __float2half(wv[i]);
    W[i + 3 * CH * CH] = __float2half(wo[i] * WO_SCALE);
}

// x [B][C][HW] fp32 -> XT [B*HW][C] f16
__global__ void xt_kernel(const float* __restrict__ x, f16* __restrict__ XT) {
    __shared__ float tile[32][33];
    const int b  = blockIdx.z;
    const int s0 = blockIdx.x * 32;
    const int c0 = blockIdx.y * 32;
    const int tx = threadIdx.x, ty = threadIdx.y;
    tile[ty][tx] = x[((size_t)b * CH + c0 + ty) * HWDIM + s0 + tx];
    __syncthreads();
    XT[((size_t)b * HWDIM + s0 + ty) * CH + c0 + tx] = __float2half(tile[tx][ty]);
}

// 1/rowsum of exp-scores P; warp per row
__global__ void rowsum_kernel(const f16* __restrict__ P, float* __restrict__ RS) {
    const int row  = blockIdx.x * 8 + (threadIdx.x >> 5);
    const int lane = threadIdx.x & 31;
    const uint4* p = (const uint4*)(P + (size_t)row * HWDIM);
    float s = 0.f;
    #pragma unroll
    for (int j = 0; j < 4; ++j) {
        uint4 v = p[lane + j * 32];
        const __half2* h = (const __half2*)&v;
        #pragma unroll
        for (int t = 0; t < 4; ++t) { float2 f = __half22float2(h[t]); s += f.x + f.y; }
    }
    #pragma unroll
    for (int o = 16; o > 0; o >>= 1) s += __shfl_xor_sync(0xffffffffu, s, o);
    if (lane == 0) RS[row] = 1.f / s;
}

// ---------------- GEMM: C[m,n] = sum_k A[m,k]*B[n,k], f16 accum -----------------
// CTA tile 128x256 (BK=32); 8 warps of 64x64 (2m x 4n). cp.async double buffer.
// EPI 0: f16 out, dual col-bias (cols [0,512)->bias1, rest bias2)
// EPI 1: f16 out, per-row bias
// EPI 2: f16 out = exp(acc*scale)
// EPI 3: fp32 out at [b][r][s] (col n = b*1024+s): acc*WO_UNSCALE + row bias + residual
// EPI 4: f16 out, row-scaled by aux[z*1024 + r]
template<int EPI>
__global__ void __launch_bounds__(256, 2)
gemm_kernel(const f16* __restrict__ A, const f16* __restrict__ B,
            void* __restrict__ Cout,
            int K, int lda, int ldb, int ldc,
            size_t sA_batch, size_t sB_batch, size_t sC_batch,
            const float* __restrict__ bias1, const float* __restrict__ bias2,
            const float* __restrict__ aux, float scale)
{
    constexpr int BM = 128, BN = 256, BK = 32;
    constexpr int LDS = BK + 8;                 // 40 halves = 80 B rows (16B-mult)
    constexpr int ASZ = BM * LDS;               // per-stage A halves
    constexpr int BSZ = BN * LDS;
    extern __shared__ f16 smem[];
    f16* sA = smem;              // [2][ASZ]
    f16* sB = smem + 2 * ASZ;    // [2][BSZ]

    const int tid  = threadIdx.x;
    const int lane = tid & 31;
    const int warp = tid >> 5;
    const int wm   = warp >> 2;       // 0..1   (64 rows)
    const int wn   = warp & 3;        // 0..3   (64 cols)
    const int bm0  = blockIdx.y * BM;
    const int bn0  = blockIdx.x * BN;
    const int z    = blockIdx.z;

    const f16* Ab = A + (size_t)z * sA_batch;
    const f16* Bb = B + (size_t)z * sB_batch;

    // producer mapping: 16B chunks; A: 512 chunks -> 2/thread, B: 1024 -> 4/thread
    const int arow = tid >> 1;                 // 0..127
    const int acol = (tid & 1) * 16;           // halves: 0 / 16
    const int brow = tid >> 2;                 // 0..63 (x4 row groups of 64)
    const int bcol = (tid & 3) * 8;            // 0,8,16,24

    const f16* gA = Ab + (size_t)(bm0 + arow) * lda + acol;
    const f16* gB = Bb + (size_t)(bn0 + brow) * ldb + bcol;
    f16* swA = sA + arow * LDS + acol;
    f16* swB = sB + brow * LDS + bcol;

    const int nk = K / BK;

    auto load_stage = [&](int stg, int kt) {
        const int ko = kt * BK;
        f16* dA = swA + stg * ASZ;
        f16* dB = swB + stg * BSZ;
        cp16(dA,     gA + ko);
        cp16(dA + 8, gA + ko + 8);        // second 16B of this thread's 32-half span
        #pragma unroll
        for (int i = 0; i < 4; ++i)
            cp16(dB + i * 64 * LDS, gB + (size_t)i * 64 * ldb + ko);
        cp_commit();
    };

    load_stage(0, 0);
    if (nk > 1) load_stage(1, 1);

    uint32_t acc[4][8][2];
    #pragma unroll
    for (int i = 0; i < 4; ++i)
        #pragma unroll
        for (int j = 0; j < 8; ++j) { acc[i][j][0] = 0u; acc[i][j][1] = 0u; }

    const int a_base = (wm * 64 + (lane & 15)) * LDS + (lane >> 4) * 8;
    const int b_base = (wn * 64 + (lane & 7) + ((lane >> 4) & 1) * 8) * LDS
                     + ((lane >> 3) & 1) * 8;

    for (int kt = 0; kt < nk; ++kt) {
        const int cur = kt & 1;
        if (kt + 1 < nk) cp_wait<1>(); else cp_wait<0>();
        __syncthreads();

        const f16* ca = sA + cur * ASZ;
        const f16* cb = sB + cur * BSZ;
        #pragma unroll
        for (int ks = 0; ks < 2; ++ks) {
            uint32_t af[4][4];
            #pragma unroll
            for (int mf = 0; mf < 4; ++mf)
                ldsm4(af[mf][0], af[mf][1], af[mf][2], af[mf][3],
                      &ca[a_base + mf * 16 * LDS + ks * 16]);
            uint32_t bg[8][2];
            #pragma unroll
            for (int pr = 0; pr < 4; ++pr)
                ldsm4(bg[2 * pr][0], bg[2 * pr][1], bg[2 * pr + 1][0], bg[2 * pr + 1][1],
                      &cb[b_base + pr * 16 * LDS + ks * 16]);
            #pragma unroll
            for (int mf = 0; mf < 4; ++mf)
                #pragma unroll
                for (int nf = 0; nf < 8; ++nf)
                    mma_f16(acc[mf][nf], af[mf], bg[nf]);
        }
        __syncthreads();
        if (kt + 2 < nk) load_stage(cur, kt + 2);
    }

    const int r_base = bm0 + wm * 64 + (lane >> 2);
    const int c_base = bn0 + wn * 64 + ((lane & 3) << 1);

    #pragma unroll
    for (int mf = 0; mf < 4; ++mf) {
        #pragma unroll
        for (int nf = 0; nf < 8; ++nf) {
            const int r = r_base + mf * 16;
            const int c = c_base + nf * 8;
            float2 f0 = __half22float2(*(const __half2*)&acc[mf][nf][0]); // (r,   c/c+1)
            float2 f1 = __half22float2(*(const __half2*)&acc[mf][nf][1]); // (r+8, c/c+1)

            if (EPI == 0) {
                f16* outp = (f16*)Cout + (size_t)z * sC_batch;
                const float b0 = (c < 512)     ? bias1[c]           : bias2[c - 512];
                const float b1 = (c + 1 < 512) ? bias1[c + 1]       : bias2[c + 1 - 512];
                *(__half2*)(outp + (size_t)r * ldc + c) =
                    __floats2half2_rn(f0.x + b0, f0.y + b1);
                *(__half2*)(outp + (size_t)(r + 8) * ldc + c) =
                    __floats2half2_rn(f1.x + b0, f1.y + b1);
            } else if (EPI == 1) {
                f16* outp = (f16*)Cout + (size_t)z * sC_batch;
                const float rb0 = bias1[r];
                const float rb1 = bias1[r + 8];
                *(__half2*)(outp + (size_t)r * ldc + c) =
                    __floats2half2_rn(f0.x + rb0, f0.y + rb0);
                *(__half2*)(outp + (size_t)(r + 8) * ldc + c) =
                    __floats2half2_rn(f1.x + rb1, f1.y + rb1);
            } else if (EPI == 2) {
                f16* outp = (f16*)Cout + (size_t)z * sC_batch;
                *(__half2*)(outp + (size_t)r * ldc + c) =
                    __floats2half2_rn(__expf(f0.x * scale), __expf(f0.y * scale));
                *(__half2*)(outp + (size_t)(r + 8) * ldc + c) =
                    __floats2half2_rn(__expf(f1.x * scale), __expf(f1.y * scale));
            } else if (EPI == 4) {
                f16* outp = (f16*)Cout + (size_t)z * sC_batch;
                const float rs0 = aux[z * HWDIM + r];
                const float rs1 = aux[z * HWDIM + r + 8];
                *(__half2*)(outp + (size_t)r * ldc + c) =
                    __floats2half2_rn(f0.x * rs0, f0.y * rs0);
                *(__half2*)(outp + (size_t)(r + 8) * ldc + c) =
                    __floats2half2_rn(f1.x * rs1, f1.y * rs1);
            } else {   // EPI == 3 : final fp32 out + residual
                float* outp = (float*)Cout;
                const int bb = c >> 10;
                const int s  = c & 1023;
                const size_t i0 = (size_t)bb * (CH * HWDIM) + (size_t)r * HWDIM + s;
                const size_t i1 = i0 + 8 * HWDIM;
                const float br0 = bias1[r];
                const float br1 = bias1[r + 8];
                const float2 x0 = *(const float2*)(aux + i0);
                const float2 x1 = *(const float2*)(aux + i1);
                *(float2*)(outp + i0) = make_float2(f0.x * WO_UNSCALE + br0 + x0.x,
                                                    f0.y * WO_UNSCALE + br0 + x0.y);
                *(float2*)(outp + i1) = make_float2(f1.x * WO_UNSCALE + br1 + x1.x,
                                                    f1.y * WO_UNSCALE + br1 + x1.y);
            }
        }
    }
}

// ---------------- launch -----------------------------------------------------------
static constexpr int GEMM_SMEM = (2 * 128 * 40 + 2 * 256 * 40) * (int)sizeof(f16); // 61440

extern "C" void kernel_launch(void* const* d_in, const int* in_sizes, int n_in,
                              void* d_out, int out_size)
{
    (void)in_sizes; (void)n_in; (void)out_size;
    const float* x  = (const float*)d_in[0];
    const float* Wq = (const float*)d_in[1];
    const float* bq = (const float*)d_in[2];
    const float* Wk = (const float*)d_in[3];
    const float* bk = (const float*)d_in[4];
    const float* Wv = (const float*)d_in[5];
    const float* bv = (const float*)d_in[6];
    const float* Wo = (const float*)d_in[7];
    const float* bo = (const float*)d_in[8];
    float* out = (float*)d_out;

    f16 *pW, *pXT, *pQK, *pV, *pP, *pHT;
    float *pRS;
    cudaGetSymbolAddress((void**)&pW,  g_W);
    cudaGetSymbolAddress((void**)&pXT, g_XT);
    cudaGetSymbolAddress((void**)&pQK, g_QK);
    cudaGetSymbolAddress((void**)&pV,  g_V);
    cudaGetSymbolAddress((void**)&pP,  g_P);
    cudaGetSymbolAddress((void**)&pRS, g_RS);
    cudaGetSymbolAddress((void**)&pHT, g_HT);

    cudaFuncSetAttribute(gemm_kernel<0>, cudaFuncAttributeMaxDynamicSharedMemorySize, GEMM_SMEM);
    cudaFuncSetAttribute(gemm_kernel<1>, cudaFuncAttributeMaxDynamicSharedMemorySize, GEMM_SMEM);
    cudaFuncSetAttribute(gemm_kernel<2>, cudaFuncAttributeMaxDynamicSharedMemorySize, GEMM_SMEM);
    cudaFuncSetAttribute(gemm_kernel<3>, cudaFuncAttributeMaxDynamicSharedMemorySize, GEMM_SMEM);
    cudaFuncSetAttribute(gemm_kernel<4>, cudaFuncAttributeMaxDynamicSharedMemorySize, GEMM_SMEM);

    // prep
    convert_w_kernel<<<(CH * CH) / 256, 256>>>(Wq, Wk, Wv, Wo, pW);
    xt_kernel<<<dim3(HWDIM / 32, CH / 32, BATCH), dim3(32, 32)>>>(x, pXT);

    // QK = XT * [Wq|Wk]^T : M=32768, N=1024, K=512
    gemm_kernel<0><<<dim3(1024 / 256, NALL / 128, 1), 256, GEMM_SMEM>>>(
        pXT, pW, pQK, CH, CH, CH, 1024, 0, 0, 0, bq, bk, nullptr, 1.f);

    // V = Wv * X^T (+bv rows) : M=512, N=32768 -> [c][token]
    gemm_kernel<1><<<dim3(NALL / 256, CH / 128, 1), 256, GEMM_SMEM>>>(
        pW + 2 * CH * CH, pXT, pV, CH, CH, CH, NALL, 0, 0, 0, bv, nullptr, nullptr, 1.f);

    // P_b = exp(scale * Q_b K_b^T) : per batch, M=N=1024, K=512
    gemm_kernel<2><<<dim3(1024 / 256, HWDIM / 128, BATCH), 256, GEMM_SMEM>>>(
        pQK, pQK + 512, pP, CH, 1024, 1024, HWDIM,
        (size_t)HWDIM * 1024, (size_t)HWDIM * 1024, (size_t)HWDIM * HWDIM,
        nullptr, nullptr, nullptr, 0.04419417382415922f);

    // 1/rowsums of P
    rowsum_kernel<<<NALL / 8, 256>>>(pP, pRS);

    // HT_b = (P_b * V_b^T) * rsinv : M=1024, N=512, K=1024
    gemm_kernel<4><<<dim3(CH / 256, HWDIM / 128, BATCH), 256, GEMM_SMEM>>>(
        pP, pV, pHT, HWDIM, HWDIM, NALL, CH,
        (size_t)HWDIM * HWDIM, (size_t)HWDIM, (size_t)HWDIM * CH,
        nullptr, nullptr, pRS, 1.f);

    // O = Wo_scaled * HT^T, unscale + bo + x : M=512, N=32768 -> [B][C][H][W]
    gemm_kernel<3><<<dim3(NALL / 256, CH / 128, 1), 256, GEMM_SMEM>>>(
        pW + 3 * CH * CH, pHT, out, CH, CH, CH, 0,
        0, 0, 0, bo, nullptr, x, 1.f);
}

// round 6
// speedup vs baseline: 1.2671x; 1.0032x over previous
#include <cuda_runtime.h>
#include <cuda_fp16.h>
#include <cstdint>

using f16 = __half;
#define DEVINLINE __device__ __forceinline__

static constexpr int CH    = 512;
static constexpr int HWDIM = 1024;
static constexpr int BATCH = 32;
static constexpr int NALL  = BATCH * HWDIM;   // 32768

static constexpr float WO_SCALE   = 4096.f;
static constexpr float WO_UNSCALE = 1.f / 4096.f;

// ---------------- scratch ----------------------------------------------------
__device__ f16   g_W [4 * CH * CH];
__device__ f16   g_XT[(size_t)NALL * CH];
__device__ f16   g_QK[(size_t)NALL * 2 * CH];
__device__ f16   g_V [(size_t)CH * NALL];
__device__ f16   g_P [(size_t)BATCH * HWDIM * HWDIM];
__device__ float g_RS[NALL];
__device__ f16   g_HT[(size_t)NALL * CH];

// ---------------- helpers ------------------------------------------------------
DEVINLINE void ldsm4(uint32_t& r0, uint32_t& r1, uint32_t& r2, uint32_t& r3,
                     const f16* p) {
    uint32_t addr = (uint32_t)__cvta_generic_to_shared(p);
    asm volatile("ldmatrix.sync.aligned.m8n8.x4.shared.b16 {%0,%1,%2,%3}, [%4];"
                 : "=r"(r0), "=r"(r1), "=r"(r2), "=r"(r3) : "r"(addr));
}

DEVINLINE void mma_f16(uint32_t c[2], const uint32_t a[4], const uint32_t b[2]) {
    asm volatile("mma.sync.aligned.m16n8k16.row.col.f16.f16.f16.f16 "
                 "{%0,%1},{%2,%3,%4,%5},{%6,%7},{%0,%1};"
                 : "+r"(c[0]), "+r"(c[1])
                 : "r"(a[0]), "r"(a[1]), "r"(a[2]), "r"(a[3]),
                   "r"(b[0]), "r"(b[1]));
}

DEVINLINE void cp16(f16* dst, const f16* src) {
    uint32_t d = (uint32_t)__cvta_generic_to_shared(dst);
    asm volatile("cp.async.cg.shared.global [%0], [%1], 16;" :: "r"(d), "l"(src));
}
DEVINLINE void cp_commit() { asm volatile("cp.async.commit_group;"); }
template<int N> DEVINLINE void cp_wait() {
    asm volatile("cp.async.wait_group %0;" :: "n"(N));
}

// ---------------- prep kernels ---------------------------------------------------
__global__ void convert_w_kernel(const float* __restrict__ wq, const float* __restrict__ wk,
                                 const float* __restrict__ wv, const float* __restrict__ wo,
                                 f16* __restrict__ W) {
    int i = blockIdx.x * blockDim.x + threadIdx.x;
    W[i]               = __float2half(wq[i]);
    W[i + CH * CH]     = __float2half(wk[i]);
    W[i + 2 * CH * CH] = __float2half(wv[i]);
    W[i + 3 * CH * CH] = __float2half(wo[i] * WO_SCALE);
}

// x [B][C][HW] fp32 -> XT [B*HW][C] f16
__global__ void xt_kernel(const float* __restrict__ x, f16* __restrict__ XT) {
    __shared__ float tile[32][33];
    const int b  = blockIdx.z;
    const int s0 = blockIdx.x * 32;
    const int c0 = blockIdx.y * 32;
    const int tx = threadIdx.x, ty = threadIdx.y;
    tile[ty][tx] = x[((size_t)b * CH + c0 + ty) * HWDIM + s0 + tx];
    __syncthreads();
    XT[((size_t)b * HWDIM + s0 + ty) * CH + c0 + tx] = __float2half(tile[tx][ty]);
}

// 1/rowsum of exp-scores P; warp per row
__global__ void rowsum_kernel(const f16* __restrict__ P, float* __restrict__ RS) {
    const int row  = blockIdx.x * 8 + (threadIdx.x >> 5);
    const int lane = threadIdx.x & 31;
    const uint4* p = (const uint4*)(P + (size_t)row * HWDIM);
    float s = 0.f;
    #pragma unroll
    for (int j = 0; j < 4; ++j) {
        uint4 v = p[lane + j * 32];
        const __half2* h = (const __half2*)&v;
        #pragma unroll
        for (int t = 0; t < 4; ++t) { float2 f = __half22float2(h[t]); s += f.x + f.y; }
    }
    #pragma unroll
    for (int o = 16; o > 0; o >>= 1) s += __shfl_xor_sync(0xffffffffu, s, o);
    if (lane == 0) RS[row] = 1.f / s;
}

// ---------------- GEMM: C[m,n] = sum_k A[m,k]*B[n,k], f16 accum -----------------
// CTA tile 128x256 (BK=32); 8 warps of 64x64. 3-stage cp.async pipeline,
// ONE barrier per k-tile, loads issued right after the barrier.
// EPI 0: f16 out, dual col-bias   1: f16 out, row bias   2: f16 = exp(acc*scale)
// EPI 3: fp32 [b][r][s] : acc*WO_UNSCALE + row bias + residual
// EPI 4: f16 out, row-scaled by aux
template<int EPI>
__global__ void __launch_bounds__(256, 2)
gemm_kernel(const f16* __restrict__ A, const f16* __restrict__ B,
            void* __restrict__ Cout,
            int K, int lda, int ldb, int ldc,
            size_t sA_batch, size_t sB_batch, size_t sC_batch,
            const float* __restrict__ bias1, const float* __restrict__ bias2,
            const float* __restrict__ aux, float scale)
{
    constexpr int BM = 128, BN = 256, BK = 32;
    constexpr int STAGES = 3;
    constexpr int LDS = BK + 8;                 // 40 halves = 80 B rows
    constexpr int ASZ = BM * LDS;
    constexpr int BSZ = BN * LDS;
    extern __shared__ f16 smem[];
    f16* sA = smem;                    // [STAGES][ASZ]
    f16* sB = smem + STAGES * ASZ;     // [STAGES][BSZ]

    const int tid  = threadIdx.x;
    const int lane = tid & 31;
    const int warp = tid >> 5;
    const int wm   = warp >> 2;       // 0..1   (64 rows)
    const int wn   = warp & 3;        // 0..3   (64 cols)
    const int bm0  = blockIdx.y * BM;
    const int bn0  = blockIdx.x * BN;
    const int z    = blockIdx.z;

    const f16* Ab = A + (size_t)z * sA_batch;
    const f16* Bb = B + (size_t)z * sB_batch;

    const int arow = tid >> 1;
    const int acol = (tid & 1) * 16;
    const int brow = tid >> 2;
    const int bcol = (tid & 3) * 8;

    const f16* gA = Ab + (size_t)(bm0 + arow) * lda + acol;
    const f16* gB = Bb + (size_t)(bn0 + brow) * ldb + bcol;
    f16* swA = sA + arow * LDS + acol;
    f16* swB = sB + brow * LDS + bcol;

    const int nk = K / BK;

    auto load_stage = [&](int stg, int kt) {
        const int ko = kt * BK;
        f16* dA = swA + stg * ASZ;
        f16* dB = swB + stg * BSZ;
        cp16(dA,     gA + ko);
        cp16(dA + 8, gA + ko + 8);
        #pragma unroll
        for (int i = 0; i < 4; ++i)
            cp16(dB + i * 64 * LDS, gB + (size_t)i * 64 * ldb + ko);
        cp_commit();
    };

    load_stage(0, 0);
    load_stage(1, 1);        // nk >= 16 always

    uint32_t acc[4][8][2];
    #pragma unroll
    for (int i = 0; i < 4; ++i)
        #pragma unroll
        for (int j = 0; j < 8; ++j) { acc[i][j][0] = 0u; acc[i][j][1] = 0u; }

    const int a_base = (wm * 64 + (lane & 15)) * LDS + (lane >> 4) * 8;
    const int b_base = (wn * 64 + (lane & 7) + ((lane >> 4) & 1) * 8) * LDS
                     + ((lane >> 3) & 1) * 8;

    int s_cur = 0;            // stage of tile t
    int s_nxt2 = 2;           // stage for tile t+2

    for (int kt = 0; kt < nk; ++kt) {
        // groups issued so far: min(kt+2, nk); need group kt complete
        if (kt + 2 <= nk) cp_wait<1>(); else cp_wait<0>();
        __syncthreads();

        // issue loads for tile kt+2 immediately (overlaps with MMA below)
        if (kt + 2 < nk) load_stage(s_nxt2, kt + 2);

        const f16* ca = sA + s_cur * ASZ;
        const f16* cb = sB + s_cur * BSZ;
        #pragma unroll
        for (int ks = 0; ks < 2; ++ks) {
            uint32_t af[4][4];
            #pragma unroll
            for (int mf = 0; mf < 4; ++mf)
                ldsm4(af[mf][0], af[mf][1], af[mf][2], af[mf][3],
                      &ca[a_base + mf * 16 * LDS + ks * 16]);
            uint32_t bg[8][2];
            #pragma unroll
            for (int pr = 0; pr < 4; ++pr)
                ldsm4(bg[2 * pr][0], bg[2 * pr][1], bg[2 * pr + 1][0], bg[2 * pr + 1][1],
                      &cb[b_base + pr * 16 * LDS + ks * 16]);
            #pragma unroll
            for (int mf = 0; mf < 4; ++mf)
                #pragma unroll
                for (int nf = 0; nf < 8; ++nf)
                    mma_f16(acc[mf][nf], af[mf], bg[nf]);
        }

        s_cur  = (s_cur == STAGES - 1)  ? 0 : s_cur + 1;
        s_nxt2 = (s_nxt2 == STAGES - 1) ? 0 : s_nxt2 + 1;
    }

    const int r_base = bm0 + wm * 64 + (lane >> 2);
    const int c_base = bn0 + wn * 64 + ((lane & 3) << 1);

    #pragma unroll
    for (int mf = 0; mf < 4; ++mf) {
        #pragma unroll
        for (int nf = 0; nf < 8; ++nf) {
            const int r = r_base + mf * 16;
            const int c = c_base + nf * 8;
            float2 f0 = __half22float2(*(const __half2*)&acc[mf][nf][0]);
            float2 f1 = __half22float2(*(const __half2*)&acc[mf][nf][1]);

            if (EPI == 0) {
                f16* outp = (f16*)Cout + (size_t)z * sC_batch;
                const float b0 = (c < 512)     ? bias1[c]     : bias2[c - 512];
                const float b1 = (c + 1 < 512) ? bias1[c + 1] : bias2[c + 1 - 512];
                *(__half2*)(outp + (size_t)r * ldc + c) =
                    __floats2half2_rn(f0.x + b0, f0.y + b1);
                *(__half2*)(outp + (size_t)(r + 8) * ldc + c) =
                    __floats2half2_rn(f1.x + b0, f1.y + b1);
            } else if (EPI == 1) {
                f16* outp = (f16*)Cout + (size_t)z * sC_batch;
                const float rb0 = bias1[r];
                const float rb1 = bias1[r + 8];
                *(__half2*)(outp + (size_t)r * ldc + c) =
                    __floats2half2_rn(f0.x + rb0, f0.y + rb0);
                *(__half2*)(outp + (size_t)(r + 8) * ldc + c) =
                    __floats2half2_rn(f1.x + rb1, f1.y + rb1);
            } else if (EPI == 2) {
                f16* outp = (f16*)Cout + (size_t)z * sC_batch;
                *(__half2*)(outp + (size_t)r * ldc + c) =
                    __floats2half2_rn(__expf(f0.x * scale), __expf(f0.y * scale));
                *(__half2*)(outp + (size_t)(r + 8) * ldc + c) =
                    __floats2half2_rn(__expf(f1.x * scale), __expf(f1.y * scale));
            } else if (EPI == 4) {
                f16* outp = (f16*)Cout + (size_t)z * sC_batch;
                const float rs0 = aux[z * HWDIM + r];
                const float rs1 = aux[z * HWDIM + r + 8];
                *(__half2*)(outp + (size_t)r * ldc + c) =
                    __floats2half2_rn(f0.x * rs0, f0.y * rs0);
                *(__half2*)(outp + (size_t)(r + 8) * ldc + c) =
                    __floats2half2_rn(f1.x * rs1, f1.y * rs1);
            } else {   // EPI == 3
                float* outp = (float*)Cout;
                const int bb = c >> 10;
                const int s  = c & 1023;
                const size_t i0 = (size_t)bb * (CH * HWDIM) + (size_t)r * HWDIM + s;
                const size_t i1 = i0 + 8 * HWDIM;
                const float br0 = bias1[r];
                const float br1 = bias1[r + 8];
                const float2 x0 = *(const float2*)(aux + i0);
                const float2 x1 = *(const float2*)(aux + i1);
                *(float2*)(outp + i0) = make_float2(f0.x * WO_UNSCALE + br0 + x0.x,
                                                    f0.y * WO_UNSCALE + br0 + x0.y);
                *(float2*)(outp + i1) = make_float2(f1.x * WO_UNSCALE + br1 + x1.x,
                                                    f1.y * WO_UNSCALE + br1 + x1.y);
            }
        }
    }
}

// ---------------- launch -----------------------------------------------------------
static constexpr int GEMM_SMEM = 3 * (128 * 40 + 256 * 40) * (int)sizeof(f16); // 92160

extern "C" void kernel_launch(void* const* d_in, const int* in_sizes, int n_in,
                              void* d_out, int out_size)
{
    (void)in_sizes; (void)n_in; (void)out_size;
    const float* x  = (const float*)d_in[0];
    const float* Wq = (const float*)d_in[1];
    const float* bq = (const float*)d_in[2];
    const float* Wk = (const float*)d_in[3];
    const float* bk = (const float*)d_in[4];
    const float* Wv = (const float*)d_in[5];
    const float* bv = (const float*)d_in[6];
    const float* Wo = (const float*)d_in[7];
    const float* bo = (const float*)d_in[8];
    float* out = (float*)d_out;

    f16 *pW, *pXT, *pQK, *pV, *pP, *pHT;
    float *pRS;
    cudaGetSymbolAddress((void**)&pW,  g_W);
    cudaGetSymbolAddress((void**)&pXT, g_XT);
    cudaGetSymbolAddress((void**)&pQK, g_QK);
    cudaGetSymbolAddress((void**)&pV,  g_V);
    cudaGetSymbolAddress((void**)&pP,  g_P);
    cudaGetSymbolAddress((void**)&pRS, g_RS);
    cudaGetSymbolAddress((void**)&pHT, g_HT);

    cudaFuncSetAttribute(gemm_kernel<0>, cudaFuncAttributeMaxDynamicSharedMemorySize, GEMM_SMEM);
    cudaFuncSetAttribute(gemm_kernel<1>, cudaFuncAttributeMaxDynamicSharedMemorySize, GEMM_SMEM);
    cudaFuncSetAttribute(gemm_kernel<2>, cudaFuncAttributeMaxDynamicSharedMemorySize, GEMM_SMEM);
    cudaFuncSetAttribute(gemm_kernel<3>, cudaFuncAttributeMaxDynamicSharedMemorySize, GEMM_SMEM);
    cudaFuncSetAttribute(gemm_kernel<4>, cudaFuncAttributeMaxDynamicSharedMemorySize, GEMM_SMEM);

    // prep
    convert_w_kernel<<<(CH * CH) / 256, 256>>>(Wq, Wk, Wv, Wo, pW);
    xt_kernel<<<dim3(HWDIM / 32, CH / 32, BATCH), dim3(32, 32)>>>(x, pXT);

    // QK = XT * [Wq|Wk]^T : M=32768, N=1024, K=512
    gemm_kernel<0><<<dim3(1024 / 256, NALL / 128, 1), 256, GEMM_SMEM>>>(
        pXT, pW, pQK, CH, CH, CH, 1024, 0, 0, 0, bq, bk, nullptr, 1.f);

    // V = Wv * X^T (+bv rows) : M=512, N=32768 -> [c][token]
    gemm_kernel<1><<<dim3(NALL / 256, CH / 128, 1), 256, GEMM_SMEM>>>(
        pW + 2 * CH * CH, pXT, pV, CH, CH, CH, NALL, 0, 0, 0, bv, nullptr, nullptr, 1.f);

    // P_b = exp(scale * Q_b K_b^T) : per batch, M=N=1024, K=512
    gemm_kernel<2><<<dim3(1024 / 256, HWDIM / 128, BATCH), 256, GEMM_SMEM>>>(
        pQK, pQK + 512, pP, CH, 1024, 1024, HWDIM,
        (size_t)HWDIM * 1024, (size_t)HWDIM * 1024, (size_t)HWDIM * HWDIM,
        nullptr, nullptr, nullptr, 0.04419417382415922f);

    // 1/rowsums of P
    rowsum_kernel<<<NALL / 8, 256>>>(pP, pRS);

    // HT_b = (P_b * V_b^T) * rsinv : M=1024, N=512, K=1024
    gemm_kernel<4><<<dim3(CH / 256, HWDIM / 128, BATCH), 256, GEMM_SMEM>>>(
        pP, pV, pHT, HWDIM, HWDIM, NALL, CH,
        (size_t)HWDIM * HWDIM, (size_t)HWDIM, (size_t)HWDIM * CH,
        nullptr, nullptr, pRS, 1.f);

    // O = Wo_scaled * HT^T, unscale + bo + x : M=512, N=32768 -> [B][C][H][W]
    gemm_kernel<3><<<dim3(NALL / 256, CH / 128, 1), 256, GEMM_SMEM>>>(
        pW + 3 * CH * CH, pHT, out, CH, CH, CH, 0,
        0, 0, 0, bo, nullptr, x, 1.f);
}